// round 4
// baseline (speedup 1.0000x reference)
#include <cuda_runtime.h>

// ---------------------------------------------------------------------------
// Multigrid F-cycle, 4096x4096, t=4 iterations, 2 kernels per iteration.
//   CW = DT/DX/2 = 0.05, DIAG = 1.
//   k_down: v -> r1..r7 (register-rolling fused smooth + tile-local restrict)
//   k_up  : per block: r7->r8,r9->e8->e7(3x3) -> e6..e1 tiles in smem ->
//           out = -edgestencil(v - prolong(e1)), rolling float4 rows.
// ---------------------------------------------------------------------------

#define N0 4096
#define CW 0.05f
#define UPT 512

static __device__ float g_v [N0 * N0];       // ping-pong partner for d_out
static __device__ float g_r1[2048 * 2048];
static __device__ float g_r2[1024 * 1024];
static __device__ float g_r3[ 512 *  512];
static __device__ float g_r4[ 256 *  256];
static __device__ float g_r5[ 128 *  128];
static __device__ float g_r6[  64 *   64];
static __device__ float g_r7[  32 *   32];

// load 8 consecutive floats from row yy at column x0 (inline fn: no macro traps)
static __device__ __forceinline__ void load8(const float* __restrict__ v,
                                             int yy, int x0, float* R) {
    const float4* p = (const float4*)(v + (size_t)yy * N0 + x0);
    float4 a = __ldg(p), b = __ldg(p + 1);
    R[0] = a.x; R[1] = a.y; R[2] = a.z; R[3] = a.w;
    R[4] = b.x; R[5] = b.y; R[6] = b.z; R[7] = b.w;
}

// ---------------------------------------------------------------------------
// smem restriction step (scalar; cheap after level 1)
// ---------------------------------------------------------------------------
template<int NA, int SA, int NB, int SB, int WB>
static __device__ __forceinline__ void restr_step(const float* sA, float* sB,
                                                  float* __restrict__ g,
                                                  int bx, int by, int tid) {
    #pragma unroll 1
    for (int idx = tid; idx < NB * NB; idx += 256) {
        int I = idx / NB, J = idx - I * NB;
        const float* p = sA + (2 * I) * SA + 2 * J;
        float x = 0.25f * (p[0] + p[1] + p[SA] + p[SA + 1]);
        if (NB > 1) sB[I * SB + J] = x;
        g[(by * NB + I) * WB + (bx * NB + J)] = x;
    }
}

// ---------------------------------------------------------------------------
// Kernel 1: 64x64 r1 tile per block. Each thread: 4 r1 rows x 4 cols, v rows
// loaded as 2x float4 with 2-row register reuse between steps.
// Grid (32,32), 256 threads (16 col-groups x 16 row-strips).
// ---------------------------------------------------------------------------
__global__ __launch_bounds__(256) void k_down(const float* __restrict__ v) {
    __shared__ float s1[64 * 68];
    __shared__ float s2[32 * 36];
    __shared__ float s3[16 * 20];
    __shared__ float s4[ 8 * 12];
    __shared__ float s5[ 4 *  8];
    __shared__ float s6[ 2 *  4];

    int tid = threadIdx.x;
    int bx = blockIdx.x, by = blockIdx.y;
    int Jt = tid & 15, It = tid >> 4;
    int x0 = (bx << 7) + (Jt << 3);          // 8 v-cols per thread
    int ybase = (by << 7) + (It << 3);       // 8 v-rows (+2 halo) per thread

    float A[8], B[8], C[8], D[8];            // rows y0-1, y0, y0+1, y0+2

    load8(v, max(ybase - 1, 0), x0, A);
    load8(v, ybase,             x0, B);
    load8(v, ybase + 1,         x0, C);
    load8(v, ybase + 2,         x0, D);

    int xl = max(x0 - 1, 0), xr = min(x0 + 8, N0 - 1);

    #pragma unroll
    for (int k = 0; k < 4; ++k) {
        int y0 = ybase + 2 * k;
        float hlB = __ldg(v + (size_t)y0 * N0 + xl);
        float hrB = __ldg(v + (size_t)y0 * N0 + xr);
        float hlC = __ldg(v + (size_t)(y0 + 1) * N0 + xl);
        float hrC = __ldg(v + (size_t)(y0 + 1) * N0 + xr);

        float4 o;
        float* op = (float*)&o;
        #pragma unroll
        for (int j = 0; j < 4; ++j) {
            float c00 = B[2*j], c01 = B[2*j+1], c10 = C[2*j], c11 = C[2*j+1];
            float t0  = A[2*j], t1  = A[2*j+1], b0  = D[2*j], b1  = D[2*j+1];
            float l0 = j ? B[2*j-1] : hlB;
            float l1 = j ? C[2*j-1] : hlC;
            float q0 = (j < 3) ? B[2*j+2] : hrB;
            float q1 = (j < 3) ? C[2*j+2] : hrC;
            float s = (c00 + c01 + c10 + c11)
                    + CW * ((t0 - c10) + (t1 - c11) + (c00 - b0) + (c01 - b1))
                    + CW * ((l0 - c01) + (c00 - q0) + (l1 - c11) + (c10 - q1));
            op[j] = 0.25f * s;
        }
        int Irow = (by << 6) + (It << 2) + k;
        *(float4*)(g_r1 + Irow * 2048 + (bx << 6) + (Jt << 2)) = o;
        *(float4*)(s1 + ((It << 2) + k) * 68 + (Jt << 2)) = o;

        if (k < 3) {
            #pragma unroll
            for (int i = 0; i < 8; ++i) { A[i] = C[i]; B[i] = D[i]; }
            load8(v, y0 + 3,              x0, C);
            load8(v, min(y0 + 4, N0 - 1), x0, D);
        }
    }
    __syncthreads();

    restr_step<64, 68, 32, 36, 1024>(s1, s2, g_r2, bx, by, tid); __syncthreads();
    restr_step<32, 36, 16, 20,  512>(s2, s3, g_r3, bx, by, tid); __syncthreads();
    restr_step<16, 20,  8, 12,  256>(s3, s4, g_r4, bx, by, tid); __syncthreads();
    restr_step< 8, 12,  4,  8,  128>(s4, s5, g_r5, bx, by, tid); __syncthreads();
    restr_step< 4,  8,  2,  4,   64>(s5, s6, g_r6, bx, by, tid); __syncthreads();
    restr_step< 2,  4,  1,  1,   32>(s6, s6, g_r7, bx, by, tid);
}

// ---------------------------------------------------------------------------
// correction level in smem (thread stride UPT)
// ---------------------------------------------------------------------------
template<int TC, int NL>
static __device__ __forceinline__ void correct_level(const float* __restrict__ rL,
                                                     const float* par, float* dst,
                                                     int bx, int by, int tid) {
    const int T  = TC + 2;
    const int TP = TC / 2 + 2;
    const int Or = by * TC - 1, Oc = bx * TC - 1;
    const int Pr = by * (TC / 2) - 1, Pc = bx * (TC / 2) - 1;
    #pragma unroll 1
    for (int idx = tid; idx < T * T; idx += UPT) {
        int Ii = idx / T, Jj = idx - Ii * T;
        int I = Or + Ii, J = Oc + Jj;
        float e = 0.0f;
        if (I >= 0 && I < NL && J >= 0 && J < NL) {
            int pc = (J >> 1) - Pc;
            int pr = (I >> 1) - Pr;
            float up = (I > 0)      ? par[(((I - 1) >> 1) - Pr) * TP + pc] : 0.0f;
            float dn = (I < NL - 1) ? par[(((I + 1) >> 1) - Pr) * TP + pc] : 0.0f;
            float lf = (J > 0)      ? par[pr * TP + (((J - 1) >> 1) - Pc)] : 0.0f;
            float rt = (J < NL - 1) ? par[pr * TP + (((J + 1) >> 1) - Pc)] : 0.0f;
            e = __ldg(rL + I * NL + J) - CW * (up - dn) - CW * (lf - rt);
        }
        dst[idx] = e;
    }
}

// ---------------------------------------------------------------------------
// Kernel 2: per block, 128x128 output tile.
//  Phase A (folded k_mid): r7 -> s8 -> s9 -> e8 -> e7 (only the 3x3 patch).
//  Phase B: e6..e1 tiles in smem.
//  Phase C: out = -edgestencil(v - prolong(e1)), rolling float4 rows.
// Grid (32,32), 512 threads.
// ---------------------------------------------------------------------------
__global__ __launch_bounds__(UPT) void k_up(const float* __restrict__ v,
                                            float* __restrict__ out) {
    __shared__ float sr7[32 * 32];
    __shared__ float s8 [16 * 16];
    __shared__ float s9 [ 8 *  8];
    __shared__ float e8s[16 * 16];
    __shared__ float se7[ 3 *  3];
    __shared__ float se6[ 4 *  4];
    __shared__ float se5[ 6 *  6];
    __shared__ float se4[10 * 10];
    __shared__ float se3[18 * 18];
    __shared__ float se2[34 * 34];
    __shared__ float se1[66 * 66];

    int tid = threadIdx.x;
    int bx = blockIdx.x, by = blockIdx.y;

    // --- Phase A: folded mid-levels ---
    if (tid < 256) ((float4*)sr7)[tid] = __ldg((const float4*)g_r7 + tid);
    __syncthreads();
    if (tid < 256) {
        int I = tid >> 4, J = tid & 15;
        const float* p = sr7 + (2 * I) * 32 + 2 * J;
        s8[tid] = 0.25f * (p[0] + p[1] + p[32] + p[33]);
    }
    __syncthreads();
    if (tid < 64) {
        int I = tid >> 3, J = tid & 7;
        const float* p = s8 + (2 * I) * 16 + 2 * J;
        s9[tid] = 0.25f * (p[0] + p[1] + p[16] + p[17]);
    }
    __syncthreads();
    if (tid < 256) {
        int I = tid >> 4, J = tid & 15;
        float up = (I > 0)  ? s9[((I - 1) >> 1) * 8 + (J >> 1)] : 0.0f;
        float dn = (I < 15) ? s9[((I + 1) >> 1) * 8 + (J >> 1)] : 0.0f;
        float lf = (J > 0)  ? s9[(I >> 1) * 8 + ((J - 1) >> 1)] : 0.0f;
        float rt = (J < 15) ? s9[(I >> 1) * 8 + ((J + 1) >> 1)] : 0.0f;
        e8s[tid] = s8[tid] - CW * (up - dn) - CW * (lf - rt);
    }
    __syncthreads();
    if (tid < 9) {
        int I = by - 1 + tid / 3, J = bx - 1 + tid % 3;
        float e = 0.0f;
        if (I >= 0 && I < 32 && J >= 0 && J < 32) {
            float up = (I > 0)  ? e8s[((I - 1) >> 1) * 16 + (J >> 1)] : 0.0f;
            float dn = (I < 31) ? e8s[((I + 1) >> 1) * 16 + (J >> 1)] : 0.0f;
            float lf = (J > 0)  ? e8s[(I >> 1) * 16 + ((J - 1) >> 1)] : 0.0f;
            float rt = (J < 31) ? e8s[(I >> 1) * 16 + ((J + 1) >> 1)] : 0.0f;
            e = sr7[I * 32 + J] - CW * (up - dn) - CW * (lf - rt);
        }
        se7[tid] = e;
    }
    __syncthreads();

    // --- Phase B: correction chain ---
    correct_level< 2,   64>(g_r6, se7, se6, bx, by, tid); __syncthreads();
    correct_level< 4,  128>(g_r5, se6, se5, bx, by, tid); __syncthreads();
    correct_level< 8,  256>(g_r4, se5, se4, bx, by, tid); __syncthreads();
    correct_level<16,  512>(g_r3, se4, se3, bx, by, tid); __syncthreads();
    correct_level<32, 1024>(g_r2, se3, se2, bx, by, tid); __syncthreads();
    correct_level<64, 2048>(g_r1, se2, se1, bx, by, tid); __syncthreads();

    // --- Phase C: final update, rolling rows ---
    const int o1r = 64 * by - 1, o1c = 64 * bx - 1;
    int fc = tid & 31, rg = tid >> 5;        // 32 col-groups, 16 row-strips
    int x  = (bx << 7) + (fc << 2);
    int ystart = (by << 7) + (rg << 3);      // 8 rows per thread
    int ec0 = (x >> 1) - o1c;
    int ecL = (max(x - 1, 0) >> 1) - o1c;
    int ecR = (min(x + 4, N0 - 1) >> 1) - o1c;
    int xll = max(x - 1, 0), xrr = min(x + 4, N0 - 1);

    float4 top = __ldg((const float4*)(v + (size_t)max(ystart - 1, 0) * N0 + x));
    float4 mid = __ldg((const float4*)(v + (size_t)ystart * N0 + x));

    #pragma unroll
    for (int k = 0; k < 8; ++k) {
        int y  = ystart + k;
        int yp = min(y + 1, N0 - 1);
        float4 bot = __ldg((const float4*)(v + (size_t)yp * N0 + x));
        float  lf  = __ldg(v + (size_t)y * N0 + xll);
        float  rt  = __ldg(v + (size_t)y * N0 + xrr);

        int ert = (max(y - 1, 0) >> 1) - o1r;
        int erm = (y  >> 1) - o1r;
        int erb = (yp >> 1) - o1r;

        float et0 = se1[ert * 66 + ec0], et1 = se1[ert * 66 + ec0 + 1];
        float eb0 = se1[erb * 66 + ec0], eb1 = se1[erb * 66 + ec0 + 1];
        float em0 = se1[erm * 66 + ec0], em1 = se1[erm * 66 + ec0 + 1];
        float emL = se1[erm * 66 + ecL], emR = se1[erm * 66 + ecR];

        float4 o;
        o.x = -CW * ((top.x - et0) - (bot.x - eb0)) - CW * ((lf    - emL) - (mid.y - em0));
        o.y = -CW * ((top.y - et0) - (bot.y - eb0)) - CW * ((mid.x - em0) - (mid.z - em1));
        o.z = -CW * ((top.z - et1) - (bot.z - eb1)) - CW * ((mid.y - em0) - (mid.w - em1));
        o.w = -CW * ((top.w - et1) - (bot.w - eb1)) - CW * ((mid.z - em1) - (rt    - emR));
        *(float4*)(out + (size_t)y * N0 + x) = o;

        top = mid; mid = bot;
    }
}

// ---------------------------------------------------------------------------
// Launch: 2 kernels per iteration, 4 iterations.
// ---------------------------------------------------------------------------
extern "C" void kernel_launch(void* const* d_in, const int* in_sizes, int n_in,
                              void* d_out, int out_size) {
    const float* u = (const float*)d_in[0];
    float* out = (float*)d_out;

    float* pv;
    cudaGetSymbolAddress((void**)&pv, g_v);

    const dim3 G(32, 32);
    const float* vin[4]  = { u,   pv,  out, pv  };
    float*       vout[4] = { pv,  out, pv,  out };

    for (int it = 0; it < 4; ++it) {
        k_down<<<G, 256>>>(vin[it]);
        k_up<<<G, UPT>>>(vin[it], vout[it]);
    }
}

// round 5
// speedup vs baseline: 1.0526x; 1.0526x over previous
#include <cuda_runtime.h>

// ---------------------------------------------------------------------------
// Multigrid F-cycle, 4096x4096, t=4 iterations, 3 kernels per iteration.
//   CW = DT/DX/2 = 0.05, DIAG = 1.
//   k_down : v -> r1..r7 (register-rolling fused smooth + tile-local restrict)
//   k_e1   : r7 -> r8,r9 -> e8 -> e7(3x3 patch) -> e6..e2 smem -> e1 global
//   k_final: out = -edgestencil(v - prolong(e1)), pure streaming
// ---------------------------------------------------------------------------

#define N0 4096
#define CW 0.05f

static __device__ float g_v [N0 * N0];       // ping-pong partner for d_out
static __device__ float g_r1[2048 * 2048];
static __device__ float g_e1[2048 * 2048];
static __device__ float g_r2[1024 * 1024];
static __device__ float g_r3[ 512 *  512];
static __device__ float g_r4[ 256 *  256];
static __device__ float g_r5[ 128 *  128];
static __device__ float g_r6[  64 *   64];
static __device__ float g_r7[  32 *   32];

// load 8 consecutive floats from row yy at column x0
static __device__ __forceinline__ void load8(const float* __restrict__ v,
                                             int yy, int x0, float* R) {
    const float4* p = (const float4*)(v + (size_t)yy * N0 + x0);
    float4 a = __ldg(p), b = __ldg(p + 1);
    R[0] = a.x; R[1] = a.y; R[2] = a.z; R[3] = a.w;
    R[4] = b.x; R[5] = b.y; R[6] = b.z; R[7] = b.w;
}

// ---------------------------------------------------------------------------
// smem restriction step
// ---------------------------------------------------------------------------
template<int NA, int SA, int NB, int SB, int WB>
static __device__ __forceinline__ void restr_step(const float* sA, float* sB,
                                                  float* __restrict__ g,
                                                  int bx, int by, int tid) {
    #pragma unroll 1
    for (int idx = tid; idx < NB * NB; idx += 256) {
        int I = idx / NB, J = idx - I * NB;
        const float* p = sA + (2 * I) * SA + 2 * J;
        float x = 0.25f * (p[0] + p[1] + p[SA] + p[SA + 1]);
        if (NB > 1) sB[I * SB + J] = x;
        g[(by * NB + I) * WB + (bx * NB + J)] = x;
    }
}

// ---------------------------------------------------------------------------
// Kernel 1: 64x64 r1 tile per block, register-rolling rows. Grid (32,32), 256t.
// ---------------------------------------------------------------------------
__global__ __launch_bounds__(256) void k_down(const float* __restrict__ v) {
    __shared__ float s1[64 * 68];
    __shared__ float s2[32 * 36];
    __shared__ float s3[16 * 20];
    __shared__ float s4[ 8 * 12];
    __shared__ float s5[ 4 *  8];
    __shared__ float s6[ 2 *  4];

    int tid = threadIdx.x;
    int bx = blockIdx.x, by = blockIdx.y;
    int Jt = tid & 15, It = tid >> 4;
    int x0 = (bx << 7) + (Jt << 3);
    int ybase = (by << 7) + (It << 3);

    float A[8], B[8], C[8], D[8];

    load8(v, max(ybase - 1, 0), x0, A);
    load8(v, ybase,             x0, B);
    load8(v, ybase + 1,         x0, C);
    load8(v, ybase + 2,         x0, D);

    int xl = max(x0 - 1, 0), xr = min(x0 + 8, N0 - 1);

    #pragma unroll
    for (int k = 0; k < 4; ++k) {
        int y0 = ybase + 2 * k;
        float hlB = __ldg(v + (size_t)y0 * N0 + xl);
        float hrB = __ldg(v + (size_t)y0 * N0 + xr);
        float hlC = __ldg(v + (size_t)(y0 + 1) * N0 + xl);
        float hrC = __ldg(v + (size_t)(y0 + 1) * N0 + xr);

        float4 o;
        float* op = (float*)&o;
        #pragma unroll
        for (int j = 0; j < 4; ++j) {
            float c00 = B[2*j], c01 = B[2*j+1], c10 = C[2*j], c11 = C[2*j+1];
            float t0  = A[2*j], t1  = A[2*j+1], b0  = D[2*j], b1  = D[2*j+1];
            float l0 = j ? B[2*j-1] : hlB;
            float l1 = j ? C[2*j-1] : hlC;
            float q0 = (j < 3) ? B[2*j+2] : hrB;
            float q1 = (j < 3) ? C[2*j+2] : hrC;
            float s = (c00 + c01 + c10 + c11)
                    + CW * ((t0 - c10) + (t1 - c11) + (c00 - b0) + (c01 - b1))
                    + CW * ((l0 - c01) + (c00 - q0) + (l1 - c11) + (c10 - q1));
            op[j] = 0.25f * s;
        }
        int Irow = (by << 6) + (It << 2) + k;
        *(float4*)(g_r1 + Irow * 2048 + (bx << 6) + (Jt << 2)) = o;
        *(float4*)(s1 + ((It << 2) + k) * 68 + (Jt << 2)) = o;

        if (k < 3) {
            #pragma unroll
            for (int i = 0; i < 8; ++i) { A[i] = C[i]; B[i] = D[i]; }
            load8(v, y0 + 3,              x0, C);
            load8(v, min(y0 + 4, N0 - 1), x0, D);
        }
    }
    __syncthreads();

    restr_step<64, 68, 32, 36, 1024>(s1, s2, g_r2, bx, by, tid); __syncthreads();
    restr_step<32, 36, 16, 20,  512>(s2, s3, g_r3, bx, by, tid); __syncthreads();
    restr_step<16, 20,  8, 12,  256>(s3, s4, g_r4, bx, by, tid); __syncthreads();
    restr_step< 8, 12,  4,  8,  128>(s4, s5, g_r5, bx, by, tid); __syncthreads();
    restr_step< 4,  8,  2,  4,   64>(s5, s6, g_r6, bx, by, tid); __syncthreads();
    restr_step< 2,  4,  1,  1,   32>(s6, s6, g_r7, bx, by, tid);
}

// ---------------------------------------------------------------------------
// correction level in smem (thread stride 256)
// ---------------------------------------------------------------------------
template<int TC, int NL>
static __device__ __forceinline__ void correct_level(const float* __restrict__ rL,
                                                     const float* par, float* dst,
                                                     int bx, int by, int tid) {
    const int T  = TC + 2;
    const int TP = TC / 2 + 2;
    const int Or = by * TC - 1, Oc = bx * TC - 1;
    const int Pr = by * (TC / 2) - 1, Pc = bx * (TC / 2) - 1;
    #pragma unroll 1
    for (int idx = tid; idx < T * T; idx += 256) {
        int Ii = idx / T, Jj = idx - Ii * T;
        int I = Or + Ii, J = Oc + Jj;
        float e = 0.0f;
        if (I >= 0 && I < NL && J >= 0 && J < NL) {
            int pc = (J >> 1) - Pc;
            int pr = (I >> 1) - Pr;
            float up = (I > 0)      ? par[(((I - 1) >> 1) - Pr) * TP + pc] : 0.0f;
            float dn = (I < NL - 1) ? par[(((I + 1) >> 1) - Pr) * TP + pc] : 0.0f;
            float lf = (J > 0)      ? par[pr * TP + (((J - 1) >> 1) - Pc)] : 0.0f;
            float rt = (J < NL - 1) ? par[pr * TP + (((J + 1) >> 1) - Pc)] : 0.0f;
            e = __ldg(rL + I * NL + J) - CW * (up - dn) - CW * (lf - rt);
        }
        dst[idx] = e;
    }
}

// ---------------------------------------------------------------------------
// Kernel 2: e1 chain. Per block, 64x64 e1 tile. Grid (32,32), 256 threads.
// ---------------------------------------------------------------------------
__global__ __launch_bounds__(256) void k_e1() {
    __shared__ float sr7[32 * 32];
    __shared__ float s8 [16 * 16];
    __shared__ float s9 [ 8 *  8];
    __shared__ float e8s[16 * 16];
    __shared__ float se7[ 3 *  3];
    __shared__ float se6[ 4 *  4];
    __shared__ float se5[ 6 *  6];
    __shared__ float se4[10 * 10];
    __shared__ float se3[18 * 18];
    __shared__ float se2[34 * 34];

    int tid = threadIdx.x;
    int bx = blockIdx.x, by = blockIdx.y;

    // mid-levels (redundant per block; tiny)
    ((float4*)sr7)[tid] = __ldg((const float4*)g_r7 + tid);
    __syncthreads();
    {
        int I = tid >> 4, J = tid & 15;
        const float* p = sr7 + (2 * I) * 32 + 2 * J;
        s8[tid] = 0.25f * (p[0] + p[1] + p[32] + p[33]);
    }
    __syncthreads();
    if (tid < 64) {
        int I = tid >> 3, J = tid & 7;
        const float* p = s8 + (2 * I) * 16 + 2 * J;
        s9[tid] = 0.25f * (p[0] + p[1] + p[16] + p[17]);
    }
    __syncthreads();
    {
        int I = tid >> 4, J = tid & 15;
        float up = (I > 0)  ? s9[((I - 1) >> 1) * 8 + (J >> 1)] : 0.0f;
        float dn = (I < 15) ? s9[((I + 1) >> 1) * 8 + (J >> 1)] : 0.0f;
        float lf = (J > 0)  ? s9[(I >> 1) * 8 + ((J - 1) >> 1)] : 0.0f;
        float rt = (J < 15) ? s9[(I >> 1) * 8 + ((J + 1) >> 1)] : 0.0f;
        e8s[tid] = s8[tid] - CW * (up - dn) - CW * (lf - rt);
    }
    __syncthreads();
    if (tid < 9) {
        int I = by - 1 + tid / 3, J = bx - 1 + tid % 3;
        float e = 0.0f;
        if (I >= 0 && I < 32 && J >= 0 && J < 32) {
            float up = (I > 0)  ? e8s[((I - 1) >> 1) * 16 + (J >> 1)] : 0.0f;
            float dn = (I < 31) ? e8s[((I + 1) >> 1) * 16 + (J >> 1)] : 0.0f;
            float lf = (J > 0)  ? e8s[(I >> 1) * 16 + ((J - 1) >> 1)] : 0.0f;
            float rt = (J < 31) ? e8s[(I >> 1) * 16 + ((J + 1) >> 1)] : 0.0f;
            e = sr7[I * 32 + J] - CW * (up - dn) - CW * (lf - rt);
        }
        se7[tid] = e;
    }
    __syncthreads();

    correct_level< 2,   64>(g_r6, se7, se6, bx, by, tid); __syncthreads();
    correct_level< 4,  128>(g_r5, se6, se5, bx, by, tid); __syncthreads();
    correct_level< 8,  256>(g_r4, se5, se4, bx, by, tid); __syncthreads();
    correct_level<16,  512>(g_r3, se4, se3, bx, by, tid); __syncthreads();
    correct_level<32, 1024>(g_r2, se3, se2, bx, by, tid); __syncthreads();

    // final level: e1 interior only (no halo), write straight to global
    const int Pr = by * 32 - 1, Pc = bx * 32 - 1;
    #pragma unroll 1
    for (int idx = tid; idx < 64 * 64; idx += 256) {
        int Ii = idx >> 6, Jj = idx & 63;
        int I = (by << 6) + Ii, J = (bx << 6) + Jj;
        int pc = (J >> 1) - Pc;
        int pr = (I >> 1) - Pr;
        float up = (I > 0)    ? se2[(((I - 1) >> 1) - Pr) * 34 + pc] : 0.0f;
        float dn = (I < 2047) ? se2[(((I + 1) >> 1) - Pr) * 34 + pc] : 0.0f;
        float lf = (J > 0)    ? se2[pr * 34 + (((J - 1) >> 1) - Pc)] : 0.0f;
        float rt = (J < 2047) ? se2[pr * 34 + (((J + 1) >> 1) - Pc)] : 0.0f;
        g_e1[I * 2048 + J] = __ldg(g_r1 + I * 2048 + J) - CW * (up - dn) - CW * (lf - rt);
    }
}

// ---------------------------------------------------------------------------
// Kernel 3: pure streaming final update.
// out[y, x..x+3] = -CW*( (vt_top - vt_bot) + (vt_left - vt_right) )
// vt(a,b) = v[a,b] - e1[a>>1, b>>1], clamped replicate BC.
// Block 256 threads = one 1024-float row quarter. Grid (4, 4096).
// ---------------------------------------------------------------------------
__global__ __launch_bounds__(256) void k_final(const float* __restrict__ v,
                                               const float* __restrict__ e1,
                                               float* __restrict__ out) {
    int x = ((blockIdx.x << 8) + threadIdx.x) << 2;
    int y = blockIdx.y;
    int ym = max(y - 1, 0), yp = min(y + 1, N0 - 1);
    int xl = max(x - 1, 0), xr = min(x + 4, N0 - 1);
    int xc = x >> 1;

    float4 top = __ldg((const float4*)(v + (size_t)ym * N0 + x));
    float4 mid = __ldg((const float4*)(v + (size_t)y  * N0 + x));
    float4 bot = __ldg((const float4*)(v + (size_t)yp * N0 + x));
    float  lf  = __ldg(v + (size_t)y * N0 + xl);
    float  rt  = __ldg(v + (size_t)y * N0 + xr);

    const float* et = e1 + (ym >> 1) * 2048;
    const float* em = e1 + (y  >> 1) * 2048;
    const float* eb = e1 + (yp >> 1) * 2048;
    float2 e_t = __ldg((const float2*)(et + xc));
    float2 e_m = __ldg((const float2*)(em + xc));
    float2 e_b = __ldg((const float2*)(eb + xc));
    float  emL = __ldg(em + (xl >> 1));
    float  emR = __ldg(em + (xr >> 1));

    float4 o;
    o.x = -CW * ((top.x - e_t.x) - (bot.x - e_b.x)) - CW * ((lf    - emL)   - (mid.y - e_m.x));
    o.y = -CW * ((top.y - e_t.x) - (bot.y - e_b.x)) - CW * ((mid.x - e_m.x) - (mid.z - e_m.y));
    o.z = -CW * ((top.z - e_t.y) - (bot.z - e_b.y)) - CW * ((mid.y - e_m.x) - (mid.w - e_m.y));
    o.w = -CW * ((top.w - e_t.y) - (bot.w - e_b.y)) - CW * ((mid.z - e_m.y) - (rt    - emR));
    *(float4*)(out + (size_t)y * N0 + x) = o;
}

// ---------------------------------------------------------------------------
// Launch: 3 kernels per iteration, 4 iterations.
// ---------------------------------------------------------------------------
extern "C" void kernel_launch(void* const* d_in, const int* in_sizes, int n_in,
                              void* d_out, int out_size) {
    const float* u = (const float*)d_in[0];
    float* out = (float*)d_out;

    float *pv, *pe1;
    cudaGetSymbolAddress((void**)&pv,  g_v);
    cudaGetSymbolAddress((void**)&pe1, g_e1);

    const dim3 G(32, 32);
    const dim3 GF(4, 4096);
    const float* vin[4]  = { u,   pv,  out, pv  };
    float*       vout[4] = { pv,  out, pv,  out };

    for (int it = 0; it < 4; ++it) {
        k_down<<<G, 256>>>(vin[it]);
        k_e1<<<G, 256>>>();
        k_final<<<GF, 256>>>(vin[it], pe1, vout[it]);
    }
}